// round 5
// baseline (speedup 1.0000x reference)
#include <cuda_runtime.h>

#define N_NODES 2000
#define N_EDGES 16000
#define BB 4
#define L1D 12
#define IN_DIM 16
#define REF 32
#define HID 32
#define OUTD 16
#define NB (N_NODES*BB)   // 8000
#define MAXDEG 128

typedef unsigned long long u64;
typedef unsigned int u32;

// ---------------- scratch (device globals; no allocation) ----------------
__device__ float g_state[NB*L1D*HID];   // [n][b][l][h]
__device__ float g_A[NB*2048];          // A[nb][c], c=k*32+h, k=0..63 (b_metaW folded in)
__device__ float g_Bm[NB*2048];         // Bm[nb][c]
__device__ float g_P1[NB*L1D*HID];      // state @ A1
__device__ float g_P4[NB*L1D*HID];      // state @ B2
__device__ float g_mbs[NB*HID];
__device__ float g_mbd[NB*HID];
__device__ int   g_offsets[N_NODES+1];
__device__ int   g_sorted[N_EDGES];

// ---------------- f32x2 packed helpers (Blackwell) ----------------
__device__ __forceinline__ u64 pk2(float lo, float hi) {
    u64 r; asm("mov.b64 %0, {%1,%2};" : "=l"(r) : "f"(lo), "f"(hi)); return r;
}
__device__ __forceinline__ u64 pk2s(float v) { return pk2(v, v); }
__device__ __forceinline__ void upk2(float& lo, float& hi, u64 v) {
    asm("mov.b64 {%0,%1}, %2;" : "=f"(lo), "=f"(hi) : "l"(v));
}
__device__ __forceinline__ u64 fma2(u64 a, u64 b, u64 c) {
    u64 d; asm("fma.rn.f32x2 %0, %1, %2, %3;" : "=l"(d) : "l"(a), "l"(b), "l"(c)); return d;
}
__device__ __forceinline__ u64 add2(u64 a, u64 b) {
    u64 d; asm("add.rn.f32x2 %0, %1, %2;" : "=l"(d) : "l"(a), "l"(b)); return d;
}

// ---------------- cp.async helpers ----------------
__device__ __forceinline__ void cpa16(u32 s, const void* g) {
    asm volatile("cp.async.cg.shared.global [%0], [%1], 16;" :: "r"(s), "l"(g));
}
__device__ __forceinline__ void cpcommit() {
    asm volatile("cp.async.commit_group;");
}
template<int N> __device__ __forceinline__ void cpwait() {
    asm volatile("cp.async.wait_group %0;" :: "n"(N));
}

// ---------------- L1: single-block hist + scan + scatter ----------------
__global__ void k_sortall(const int* __restrict__ dst) {
    __shared__ int cnt[N_NODES];
    __shared__ int sb[1024];
    int t = threadIdx.x;   // 1024
    for (int i = t; i < N_NODES; i += 1024) cnt[i] = 0;
    __syncthreads();
    for (int e = t; e < N_EDGES; e += 1024) atomicAdd(&cnt[dst[e]], 1);
    __syncthreads();
    int i0 = 2*t, i1 = 2*t + 1;
    int a0 = (i0 < N_NODES) ? cnt[i0] : 0;
    int a1 = (i1 < N_NODES) ? cnt[i1] : 0;
    sb[t] = a0 + a1;
    __syncthreads();
    for (int off = 1; off < 1024; off <<= 1) {
        int v = (t >= off) ? sb[t - off] : 0;
        __syncthreads();
        sb[t] += v;
        __syncthreads();
    }
    int excl = sb[t] - (a0 + a1);
    if (i0 < N_NODES) g_offsets[i0] = excl;
    if (i1 < N_NODES) g_offsets[i1] = excl + a0;
    if (t == 1023) g_offsets[N_NODES] = sb[1023];
    __syncthreads();
    if (i0 < N_NODES) cnt[i0] = excl;
    if (i1 < N_NODES) cnt[i1] = excl + a0;
    __syncthreads();
    for (int e = t; e < N_EDGES; e += 1024) {
        int d = dst[e];
        int pos = atomicAdd(&cnt[d], 1);
        g_sorted[pos] = e;     // arbitrary in-bin order; k_main rank-sorts
    }
}

// ---------------- L2: state = x @ W_in + b_in  (node-major) ----------------
__global__ void k_state(const float* __restrict__ x, const float* __restrict__ W_in,
                        const float* __restrict__ b_in) {
    int n = blockIdx.x;
    __shared__ float xs[BB*L1D*IN_DIM];   // 768
    __shared__ float ws[IN_DIM*HID];      // 512
    __shared__ float bs[HID];
    int t = threadIdx.x;   // 256
    for (int i = t; i < IN_DIM*HID; i += 256) ws[i] = W_in[i];
    if (t < HID) bs[t] = b_in[t];
    for (int i = t; i < BB*L1D*IN_DIM; i += 256) {
        int bl = i / IN_DIM, ii = i % IN_DIM;
        int b = bl / L1D, l = bl % L1D;
        xs[i] = x[((b*L1D + l)*N_NODES + n)*IN_DIM + ii];
    }
    __syncthreads();
    for (int o = t; o < BB*L1D*HID; o += 256) {
        int h = o % HID, bl = o / HID;
        float acc = bs[h];
        #pragma unroll
        for (int i = 0; i < IN_DIM; i++)
            acc = fmaf(xs[bl*IN_DIM + i], ws[i*HID + h], acc);
        g_state[n*(BB*L1D*HID) + o] = acc;
    }
}

// ---------------- L3: fused hypernetwork GEMM + P1/P4/mbs/mbd ----------------
// 250 blocks x 256 threads; each block owns 32 nb rows end-to-end.
__global__ void __launch_bounds__(256) k_metapmb(const float* __restrict__ mk,
                                                 const float* __restrict__ W,
                                                 const float* __restrict__ bW,
                                                 const float* __restrict__ Wmb,
                                                 const float* __restrict__ bmb) {
    __shared__ __align__(16) float mks[1024];   // 32 nb x 32 ref
    __shared__ __align__(16) float shW[8192];   // phase1: wA|wB; phase2: aA|aB|stt
    int t = threadIdx.x;
    int nb0 = blockIdx.x * 32;

    for (int i = t; i < 1024; i += 256) {
        int row = i >> 5, r = i & 31;
        int nb = nb0 + row, n = nb >> 2, b = nb & 3;
        mks[i] = mk[(b*N_NODES + n)*REF + r];
    }

    // ---- Phase 1: [32 x 32] @ [32 x 2048] for both A and Bm halves ----
    float* wA = shW;
    float* wB = shW + 4096;
    int tc = t & 15, tr = t >> 4;          // 16 col-groups x 16 row-groups
    int row0 = tr * 2, col0 = tc * 8;
    for (int ct = 0; ct < 16; ct++) {
        int c0 = ct * 128;
        __syncthreads();
        for (int i = t; i < 1024; i += 256) {
            int r = (i*4) >> 7, c = (i*4) & 127;
            *(float4*)&wA[r*128 + c] = *(const float4*)&W[r*2048 + c0 + c];
            *(float4*)&wB[r*128 + c] = *(const float4*)&W[(r + 32)*2048 + c0 + c];
        }
        __syncthreads();
        u64 accA[2][4], accB[2][4];
        #pragma unroll
        for (int i = 0; i < 2; i++)
            #pragma unroll
            for (int j = 0; j < 4; j++) { accA[i][j] = 0ull; accB[i][j] = 0ull; }
        #pragma unroll 8
        for (int r = 0; r < 32; r++) {
            ulonglong2 wa0 = *(const ulonglong2*)&wA[r*128 + col0];
            ulonglong2 wa1 = *(const ulonglong2*)&wA[r*128 + col0 + 4];
            ulonglong2 wb0 = *(const ulonglong2*)&wB[r*128 + col0];
            ulonglong2 wb1 = *(const ulonglong2*)&wB[r*128 + col0 + 4];
            #pragma unroll
            for (int i = 0; i < 2; i++) {
                u64 a = pk2s(mks[(row0 + i)*32 + r]);
                accA[i][0] = fma2(a, wa0.x, accA[i][0]);
                accA[i][1] = fma2(a, wa0.y, accA[i][1]);
                accA[i][2] = fma2(a, wa1.x, accA[i][2]);
                accA[i][3] = fma2(a, wa1.y, accA[i][3]);
                accB[i][0] = fma2(a, wb0.x, accB[i][0]);
                accB[i][1] = fma2(a, wb0.y, accB[i][1]);
                accB[i][2] = fma2(a, wb1.x, accB[i][2]);
                accB[i][3] = fma2(a, wb1.y, accB[i][3]);
            }
        }
        ulonglong2 bv0 = *(const ulonglong2*)&bW[c0 + col0];
        ulonglong2 bv1 = *(const ulonglong2*)&bW[c0 + col0 + 4];
        #pragma unroll
        for (int i = 0; i < 2; i++) {
            int nb = nb0 + row0 + i;
            ulonglong2 oa0, oa1, ob0, ob1;
            oa0.x = add2(accA[i][0], bv0.x); oa0.y = add2(accA[i][1], bv0.y);
            oa1.x = add2(accA[i][2], bv1.x); oa1.y = add2(accA[i][3], bv1.y);
            ob0.x = accB[i][0]; ob0.y = accB[i][1];
            ob1.x = accB[i][2]; ob1.y = accB[i][3];
            *(ulonglong2*)&g_A[nb*2048 + c0 + col0]      = oa0;
            *(ulonglong2*)&g_A[nb*2048 + c0 + col0 + 4]  = oa1;
            *(ulonglong2*)&g_Bm[nb*2048 + c0 + col0]     = ob0;
            *(ulonglong2*)&g_Bm[nb*2048 + c0 + col0 + 4] = ob1;
        }
    }

    // ---- Phase 2: per-nb P1 = state@A1, P4 = state@B2, mbs/mbd ----
    float* aA  = shW;          // 1024
    float* aB  = shW + 1024;   // 1024
    float* stt = shW + 2048;   // 384
    for (int i2 = 0; i2 < 32; i2++) {
        int nb = nb0 + i2, n = nb >> 2, b = nb & 3;
        __syncthreads();
        if (t < 256) {
            ((float4*)aA)[t] = ((const float4*)&g_A[nb*2048])[t];
            ((float4*)aB)[t] = ((const float4*)&g_Bm[nb*2048 + 1024])[t];
        }
        if (t < 96) ((float4*)stt)[t] = ((const float4*)&g_state[nb*384])[t];
        __syncthreads();
        int h = t & 31, lsel = t >> 5;
        #pragma unroll
        for (int jj = 0; jj < 2; jj++) {
            int l = lsel + 8*jj;
            if (l < L1D) {
                float p1 = 0.f, p4 = 0.f;
                #pragma unroll
                for (int k = 0; k < HID; k++) {
                    float s = stt[l*32 + k];
                    p1 = fmaf(s, aA[k*32 + h], p1);
                    p4 = fmaf(s, aB[k*32 + h], p4);
                }
                g_P1[nb*384 + l*32 + h] = p1;
                g_P4[nb*384 + l*32 + h] = p4;
            }
        }
        if (t < HID) {
            float s1 = 0.f, s2 = bmb[t];
            #pragma unroll
            for (int r = 0; r < REF; r++) {
                float m = __ldg(&mk[(b*N_NODES + n)*REF + r]);
                s1 = fmaf(m, __ldg(&Wmb[r*HID + t]), s1);
                s2 = fmaf(m, __ldg(&Wmb[(r + REF)*HID + t]), s2);
            }
            g_mbs[nb*HID + t] = s1;
            g_mbd[nb*HID + t] = s2;
        }
    }
}

// ---------------- L4: k_main — 4 warps per (dst,b), edge-strided ----------------
// dynamic smem layout (floats):
#define O_B1D   0          // 1024
#define O_STDS  1024       // 396  (12*33)
#define O_P4M   1420       // 432  (12*36)
#define O_NEWS  1852       // 384
#define O_WOUT  2236       // 512
#define O_SLIST 2748       // 128 ints
#define O_EKEYS 2876       // 128 ints
#define O_PW    3004       // 4 x PW_SIZE
#define PW_SIZE 3840       // A2b 2x1024 | stsS 2x432 | P1s 2x432 | mbsS 2x32
#define SMEM_MAIN ((O_PW + 4*PW_SIZE)*4)   // 73456 bytes

__global__ void __launch_bounds__(128) k_main(const int* __restrict__ src,
                                              const float* __restrict__ W_out,
                                              const float* __restrict__ b_out,
                                              float* __restrict__ out) {
    extern __shared__ __align__(16) float sh[];
    float* B1d  = sh + O_B1D;
    float* stds = sh + O_STDS;
    float* P4m  = sh + O_P4M;
    float* news = sh + O_NEWS;
    float* wout = sh + O_WOUT;
    int*   slist = (int*)(sh + O_SLIST);
    int*   ekeys = (int*)(sh + O_EKEYS);

    int t = threadIdx.x, wid = t >> 5, lane = t & 31;
    int nbd = blockIdx.x, n = nbd >> 2, b = nbd & 3;
    int es = g_offsets[n];
    int deg = g_offsets[n+1] - es;
    if (deg > MAXDEG) deg = MAXDEG;

    if (t < deg) ekeys[t] = g_sorted[es + t];

    // prologue: dst-side fixed data (128 threads cooperative)
    for (int i = t; i < 256; i += 128)
        ((float4*)B1d)[i] = ((const float4*)&g_Bm[(size_t)nbd*2048])[i];
    for (int i = t; i < 384; i += 128) {
        int l = i >> 5, k = i & 31;
        stds[l*33 + k] = g_state[nbd*384 + i];
        P4m[l*36 + k] = g_P4[nbd*384 + i] + g_mbd[nbd*32 + k];
    }
    if (t < 128) ((float4*)wout)[t] = ((const float4*)W_out)[t];
    __syncthreads();

    // deterministic rank-sort of bin by edge id; store src node
    if (t < deg) {
        int key = ekeys[t], r = 0;
        for (int j = 0; j < deg; j++) r += (ekeys[j] < key);
        slist[r] = src[key];
    }
    __syncthreads();

    // per-warp buffers
    float* A2b  = sh + O_PW + wid*PW_SIZE;   // 2 x 1024
    float* stsS = A2b + 2048;                // 2 x 432 (12*36)
    float* P1s  = A2b + 2912;                // 2 x 432
    float* mbsS = A2b + 3776;                // 2 x 32
    u32 sA2 = (u32)__cvta_generic_to_shared(A2b);
    u32 sSt = (u32)__cvta_generic_to_shared(stsS);
    u32 sP1 = (u32)__cvta_generic_to_shared(P1s);
    u32 sMb = (u32)__cvta_generic_to_shared(mbsS);

    int lg = lane >> 3, hg = lane & 7, h4 = hg * 4;
    int l0 = lg * 3;
    int cnt = (deg > wid) ? ((deg - wid + 3) >> 2) : 0;

    u64 num[3][2], den[3][2];
    #pragma unroll
    for (int j = 0; j < 3; j++) { num[j][0]=num[j][1]=den[j][0]=den[j][1]=0ull; }

    auto prefetch = [&](int m, int v) {
        int nbs = slist[wid + 4*m]*4 + b;
        u32 vb = v * 4096;          // A2 buffer byte offset
        u32 vs = v * 1728;          // sts/P1 buffer byte offset
        const float* pa = &g_A[(size_t)nbs*2048 + 1024];
        #pragma unroll
        for (int r = 0; r < 8; r++) {
            int c = lane + 32*r;
            cpa16(sA2 + vb + c*16, pa + c*4);
        }
        const float* ps = &g_state[nbs*384];
        const float* pp = &g_P1[nbs*384];
        #pragma unroll
        for (int r = 0; r < 3; r++) {
            int c = lane + 32*r;
            int l = c >> 3, c4 = (c & 7) * 4;
            u32 off = (l*36 + c4) * 4;
            cpa16(sSt + vs + off, ps + c*4);
            cpa16(sP1 + vs + off, pp + c*4);
        }
        if (lane < 8) cpa16(sMb + v*128 + lane*16, &g_mbs[nbs*32 + lane*4]);
    };

    if (cnt > 0) { prefetch(0, 0); cpcommit(); }

    for (int m = 0; m < cnt; m++) {
        int v = m & 1;
        if (m + 1 < cnt) {
            prefetch(m + 1, v ^ 1);
            cpcommit();
            cpwait<1>();
        } else {
            cpwait<0>();
        }
        __syncwarp();

        float* A2v = A2b + v*1024;
        float* stv = stsS + v*432;
        float* p1v = P1s + v*432;
        float* mbv = mbsS + v*32;

        u64 att[3][2];
        float4 mb4 = *(float4*)&mbv[h4];
        #pragma unroll
        for (int j = 0; j < 3; j++) {
            int l = l0 + j;
            float4 p1 = *(float4*)&p1v[l*36 + h4];
            float4 p4 = *(float4*)&P4m[l*36 + h4];
            att[j][0] = pk2(p1.x + p4.x + mb4.x, p1.y + p4.y + mb4.y);
            att[j][1] = pk2(p1.z + p4.z + mb4.z, p1.w + p4.w + mb4.w);
        }
        #pragma unroll 16
        for (int k = 0; k < 32; k++) {
            ulonglong2 bb = *(const ulonglong2*)&B1d[k*32 + h4];
            ulonglong2 aa = *(const ulonglong2*)&A2v[k*32 + h4];
            #pragma unroll
            for (int j = 0; j < 3; j++) {
                int l = l0 + j;
                u64 ss = pk2s(stv[l*36 + k]);
                u64 dd = pk2s(stds[l*33 + k]);
                att[j][0] = fma2(ss, bb.x, att[j][0]);
                att[j][1] = fma2(ss, bb.y, att[j][1]);
                att[j][0] = fma2(dd, aa.x, att[j][0]);
                att[j][1] = fma2(dd, aa.y, att[j][1]);
            }
        }
        #pragma unroll
        for (int j = 0; j < 3; j++) {
            int l = l0 + j;
            float a0,a1,a2,a3;
            upk2(a0, a1, att[j][0]); upk2(a2, a3, att[j][1]);
            float e0 = __expf(a0), e1 = __expf(a1), e2 = __expf(a2), e3 = __expf(a3);
            u64 ep0 = pk2(e0, e1), ep1 = pk2(e2, e3);
            den[j][0] = add2(den[j][0], ep0);
            den[j][1] = add2(den[j][1], ep1);
            float4 sv = *(float4*)&stv[l*36 + h4];
            num[j][0] = fma2(ep0, pk2(sv.x, sv.y), num[j][0]);
            num[j][1] = fma2(ep1, pk2(sv.z, sv.w), num[j][1]);
        }
        __syncwarp();
    }
    __syncwarp();

    // write this warp's partial num/den into its (now dead) A2 buffer
    {
        float* cw = A2b;
        #pragma unroll
        for (int j = 0; j < 3; j++) {
            int l = l0 + j;
            float n0,n1,n2,n3,d0,d1,d2,d3;
            upk2(n0, n1, num[j][0]); upk2(n2, n3, num[j][1]);
            upk2(d0, d1, den[j][0]); upk2(d2, d3, den[j][1]);
            float4 nv = {n0, n1, n2, n3};
            float4 dv = {d0, d1, d2, d3};
            *(float4*)&cw[l*32 + h4]       = nv;
            *(float4*)&cw[384 + l*32 + h4] = dv;
        }
    }
    __syncthreads();

    // combine across warps -> news
    for (int idx = t; idx < 384; idx += 128) {
        float ns = 0.f, ds = 0.f;
        #pragma unroll
        for (int w = 0; w < 4; w++) {
            const float* cw = sh + O_PW + w*PW_SIZE;
            ns += cw[idx];
            ds += cw[384 + idx];
        }
        news[idx] = __fdividef(ns, ds == 0.f ? 1.f : ds);
    }
    __syncthreads();

    // output projection: 192 outputs over 128 threads
    for (int oi = t; oi < L1D*OUTD; oi += 128) {
        int l = oi >> 4, o = oi & 15;
        float acc = b_out[o];
        #pragma unroll
        for (int h = 0; h < HID; h++)
            acc = fmaf(news[l*32 + h], wout[h*16 + o], acc);
        out[((b*L1D + l)*N_NODES + n)*OUTD + o] = acc;
    }
}

// ---------------- launch ----------------
extern "C" void kernel_launch(void* const* d_in, const int* in_sizes, int n_in,
                              void* d_out, int out_size) {
    const float* long_states = (const float*)d_in[0];   // [B,N,REF]
    const float* short_in    = (const float*)d_in[1];   // [B,L1,N,IN]
    const int*   src         = (const int*)d_in[2];
    const int*   dst         = (const int*)d_in[3];
    const float* W_in        = (const float*)d_in[4];
    const float* b_in        = (const float*)d_in[5];
    const float* W_metaW     = (const float*)d_in[6];
    const float* b_metaW     = (const float*)d_in[7];
    const float* W_metab     = (const float*)d_in[8];
    const float* b_metab     = (const float*)d_in[9];
    const float* W_out       = (const float*)d_in[10];
    const float* b_out       = (const float*)d_in[11];
    float* out = (float*)d_out;

    cudaFuncSetAttribute(k_main, cudaFuncAttributeMaxDynamicSharedMemorySize, SMEM_MAIN);

    k_sortall<<<1, 1024>>>(dst);
    k_state<<<N_NODES, 256>>>(short_in, W_in, b_in);
    k_metapmb<<<NB/32, 256>>>(long_states, W_metaW, b_metaW, W_metab, b_metab);
    k_main<<<NB, 128, SMEM_MAIN>>>(src, W_out, b_out, out);
}

// round 6
// speedup vs baseline: 1.5588x; 1.5588x over previous
#include <cuda_runtime.h>

#define N_NODES 2000
#define N_EDGES 16000
#define BB 4
#define L1D 12
#define IN_DIM 16
#define REF 32
#define HID 32
#define OUTD 16
#define NB (N_NODES*BB)   // 8000
#define MAXDEG 128

typedef unsigned long long u64;
typedef unsigned int u32;

// ---------------- scratch (device globals; no allocation) ----------------
__device__ float g_state[NB*L1D*HID];   // [n][b][l][h]
__device__ float g_A[NB*2048];          // A[nb][c], c=k*32+h, k=0..63 (b_metaW folded in)
__device__ float g_Bm[NB*2048];         // Bm[nb][c]
__device__ float g_P1[NB*L1D*HID];      // state @ A1
__device__ float g_P4[NB*L1D*HID];      // state @ B2
__device__ float g_mbs[NB*HID];
__device__ float g_mbd[NB*HID];
__device__ int   g_counts[N_NODES];
__device__ int   g_cursor[N_NODES];
__device__ int   g_offsets[N_NODES+1];
__device__ int   g_sorted[N_EDGES];

// ---------------- f32x2 packed helpers (Blackwell) ----------------
__device__ __forceinline__ u64 pk2(float lo, float hi) {
    u64 r; asm("mov.b64 %0, {%1,%2};" : "=l"(r) : "f"(lo), "f"(hi)); return r;
}
__device__ __forceinline__ u64 pk2s(float v) { return pk2(v, v); }
__device__ __forceinline__ void upk2(float& lo, float& hi, u64 v) {
    asm("mov.b64 {%0,%1}, %2;" : "=f"(lo), "=f"(hi) : "l"(v));
}
__device__ __forceinline__ u64 fma2(u64 a, u64 b, u64 c) {
    u64 d; asm("fma.rn.f32x2 %0, %1, %2, %3;" : "=l"(d) : "l"(a), "l"(b), "l"(c)); return d;
}
__device__ __forceinline__ u64 add2(u64 a, u64 b) {
    u64 d; asm("add.rn.f32x2 %0, %1, %2;" : "=l"(d) : "l"(a), "l"(b)); return d;
}

// ---------------- cp.async helpers ----------------
__device__ __forceinline__ void cpa16(u32 s, const void* g) {
    asm volatile("cp.async.cg.shared.global [%0], [%1], 16;" :: "r"(s), "l"(g));
}
__device__ __forceinline__ void cpcommit() {
    asm volatile("cp.async.commit_group;");
}
template<int N> __device__ __forceinline__ void cpwait() {
    asm volatile("cp.async.wait_group %0;" :: "n"(N));
}

// ---------------- K1: state = x @ W_in + b_in  (node-major); zero hist ----------------
__global__ void k_state(const float* __restrict__ x, const float* __restrict__ W_in,
                        const float* __restrict__ b_in) {
    int n = blockIdx.x;
    __shared__ float xs[BB*L1D*IN_DIM];   // 768
    __shared__ float ws[IN_DIM*HID];      // 512
    __shared__ float bs[HID];
    int t = threadIdx.x;   // 256
    if (t == 0) g_counts[n] = 0;          // zero histogram for the sort
    for (int i = t; i < IN_DIM*HID; i += 256) ws[i] = W_in[i];
    if (t < HID) bs[t] = b_in[t];
    for (int i = t; i < BB*L1D*IN_DIM; i += 256) {
        int bl = i / IN_DIM, ii = i % IN_DIM;
        int b = bl / L1D, l = bl % L1D;
        xs[i] = x[((b*L1D + l)*N_NODES + n)*IN_DIM + ii];
    }
    __syncthreads();
    for (int o = t; o < BB*L1D*HID; o += 256) {
        int h = o % HID, bl = o / HID;
        float acc = bs[h];
        #pragma unroll
        for (int i = 0; i < IN_DIM; i++)
            acc = fmaf(xs[bl*IN_DIM + i], ws[i*HID + h], acc);
        g_state[n*(BB*L1D*HID) + o] = acc;
    }
}

// ---------------- K2: per-node hypernetwork GEMM (f32x2), grid (250,16) ----------------
__global__ void __launch_bounds__(128) k_meta(const float* __restrict__ mk,
                                              const float* __restrict__ W,
                                              const float* __restrict__ bW) {
    const int NBT = 32, CT = 128;
    int nb0 = blockIdx.x * NBT;
    int c0  = blockIdx.y * CT;
    __shared__ __align__(16) float mks[NBT][REF];
    __shared__ __align__(16) float wA[REF][CT];
    __shared__ __align__(16) float wB[REF][CT];
    int t = threadIdx.x;   // 128
    for (int i = t; i < NBT*REF; i += 128) {
        int row = i / REF, r = i % REF;
        int nb = nb0 + row, n = nb >> 2, b = nb & 3;
        mks[row][r] = mk[(b*N_NODES + n)*REF + r];
    }
    for (int i = t; i < REF*CT/4; i += 128) {
        int r = (i*4) / CT, c = (i*4) % CT;
        *(float4*)&wA[r][c] = *(const float4*)&W[r*2048 + c0 + c];
        *(float4*)&wB[r][c] = *(const float4*)&W[(r + REF)*2048 + c0 + c];
    }
    __syncthreads();
    int tc = t & 15;
    int tr = t >> 4;
    int row0 = tr * 4, col0 = tc * 8;
    u64 accA[4][4], accB[4][4];
    #pragma unroll
    for (int i = 0; i < 4; i++)
        #pragma unroll
        for (int j = 0; j < 4; j++) { accA[i][j] = 0ull; accB[i][j] = 0ull; }
    #pragma unroll 8
    for (int r = 0; r < REF; r++) {
        ulonglong2 wa0 = *(const ulonglong2*)&wA[r][col0];
        ulonglong2 wa1 = *(const ulonglong2*)&wA[r][col0+4];
        ulonglong2 wb0 = *(const ulonglong2*)&wB[r][col0];
        ulonglong2 wb1 = *(const ulonglong2*)&wB[r][col0+4];
        #pragma unroll
        for (int i = 0; i < 4; i++) {
            u64 a = pk2s(mks[row0+i][r]);
            accA[i][0] = fma2(a, wa0.x, accA[i][0]);
            accA[i][1] = fma2(a, wa0.y, accA[i][1]);
            accA[i][2] = fma2(a, wa1.x, accA[i][2]);
            accA[i][3] = fma2(a, wa1.y, accA[i][3]);
            accB[i][0] = fma2(a, wb0.x, accB[i][0]);
            accB[i][1] = fma2(a, wb0.y, accB[i][1]);
            accB[i][2] = fma2(a, wb1.x, accB[i][2]);
            accB[i][3] = fma2(a, wb1.y, accB[i][3]);
        }
    }
    ulonglong2 bv0 = *(const ulonglong2*)&bW[c0 + col0];
    ulonglong2 bv1 = *(const ulonglong2*)&bW[c0 + col0 + 4];
    #pragma unroll
    for (int i = 0; i < 4; i++) {
        int nb = nb0 + row0 + i;
        ulonglong2 oa0, oa1, ob0, ob1;
        oa0.x = add2(accA[i][0], bv0.x); oa0.y = add2(accA[i][1], bv0.y);
        oa1.x = add2(accA[i][2], bv1.x); oa1.y = add2(accA[i][3], bv1.y);
        ob0.x = accB[i][0]; ob0.y = accB[i][1];
        ob1.x = accB[i][2]; ob1.y = accB[i][3];
        *(ulonglong2*)&g_A[nb*2048 + c0 + col0]      = oa0;
        *(ulonglong2*)&g_A[nb*2048 + c0 + col0 + 4]  = oa1;
        *(ulonglong2*)&g_Bm[nb*2048 + c0 + col0]     = ob0;
        *(ulonglong2*)&g_Bm[nb*2048 + c0 + col0 + 4] = ob1;
    }
}

// ---------------- K2b: P1 = state@A1, P4 = state@B2, mbs/mbd ----------------
__global__ void k_pmb(const float* __restrict__ mk, const float* __restrict__ Wmb,
                      const float* __restrict__ bmb) {
    int nb = blockIdx.x, n = nb >> 2, b = nb & 3;
    __shared__ float st[L1D*HID];
    __shared__ float A1[1024];
    __shared__ float B2[1024];
    __shared__ float mks[REF];
    int t = threadIdx.x;  // 128
    {
        const float4* ps = reinterpret_cast<const float4*>(&g_state[nb*L1D*HID]);
        float4* ss = reinterpret_cast<float4*>(st);
        for (int i = t; i < (L1D*HID)/4; i += 128) ss[i] = ps[i];
        const float4* pa = reinterpret_cast<const float4*>(&g_A[nb*2048]);
        const float4* pb = reinterpret_cast<const float4*>(&g_Bm[nb*2048 + 1024]);
        float4* sa = reinterpret_cast<float4*>(A1);
        float4* sb = reinterpret_cast<float4*>(B2);
        for (int i = t; i < 256; i += 128) { sa[i] = pa[i]; sb[i] = pb[i]; }
    }
    if (t < REF) mks[t] = mk[(b*N_NODES + n)*REF + t];
    __syncthreads();
    int h = t & 31, l0 = t >> 5;
    #pragma unroll
    for (int j = 0; j < 3; j++) {
        int l = l0 + 4*j;
        float p1 = 0.f, p4 = 0.f;
        #pragma unroll
        for (int k = 0; k < HID; k++) {
            float s = st[l*HID + k];
            p1 = fmaf(s, A1[k*32 + h], p1);
            p4 = fmaf(s, B2[k*32 + h], p4);
        }
        g_P1[nb*(L1D*HID) + l*32 + h] = p1;
        g_P4[nb*(L1D*HID) + l*32 + h] = p4;
    }
    if (t < HID) {
        float s1 = 0.f, s2 = bmb[t];
        #pragma unroll
        for (int r = 0; r < REF; r++) {
            s1 = fmaf(mks[r], Wmb[r*HID + t], s1);
            s2 = fmaf(mks[r], Wmb[(r + REF)*HID + t], s2);
        }
        g_mbs[nb*HID + t] = s1;
        g_mbd[nb*HID + t] = s2;
    }
}

// ---------------- K3: parallel counting sort by dst (bin order fixed in k_main) ----------------
__global__ void k_hist(const int* __restrict__ dst) {
    int e = blockIdx.x*blockDim.x + threadIdx.x;
    if (e < N_EDGES) atomicAdd(&g_counts[dst[e]], 1);
}
__global__ void k_scan() {
    __shared__ int sb[1024];
    int t = threadIdx.x;
    int i0 = 2*t, i1 = 2*t + 1;
    int a0 = (i0 < N_NODES) ? g_counts[i0] : 0;
    int a1 = (i1 < N_NODES) ? g_counts[i1] : 0;
    sb[t] = a0 + a1;
    __syncthreads();
    for (int off = 1; off < 1024; off <<= 1) {
        int v = (t >= off) ? sb[t - off] : 0;
        __syncthreads();
        sb[t] += v;
        __syncthreads();
    }
    int excl = sb[t] - (a0 + a1);
    if (i0 < N_NODES) { g_offsets[i0] = excl;      g_cursor[i0] = excl; }
    if (i1 < N_NODES) { g_offsets[i1] = excl + a0; g_cursor[i1] = excl + a0; }
    if (t == 1023) g_offsets[N_NODES] = sb[1023];
}
__global__ void k_scatter(const int* __restrict__ dst) {
    int e = blockIdx.x*blockDim.x + threadIdx.x;
    if (e < N_EDGES) {
        int d = dst[e];
        int pos = atomicAdd(&g_cursor[d], 1);
        g_sorted[pos] = e;
    }
}

// ---------------- K4: k_main — 4 warps per (dst,b), edge-strided, 55KB smem ----------------
// smem layout (floats):
#define O_STDS  1024       // stds 12*36 = 432
#define O_NEWS  1456       // 384
#define O_SLIST 1840       // 128 ints
#define O_EKEYS 1968       // 128 ints
#define O_PW    2096       // 4 x PW_WORDS
#define PW_WORDS 2912      // A2b 2x1024 | stsS 2x432
#define SMEM_MAIN ((O_PW + 4*PW_WORDS)*4)   // 54976 bytes -> 4 blocks/SM

__global__ void __launch_bounds__(128, 4) k_main(const int* __restrict__ src,
                                                 const float* __restrict__ W_out,
                                                 const float* __restrict__ b_out,
                                                 float* __restrict__ out) {
    extern __shared__ __align__(16) float sh[];
    float* B1d  = sh;                 // 1024, dst-fixed
    float* stds = sh + O_STDS;        // 12*36, dst-fixed, bank-padded
    float* news = sh + O_NEWS;
    int*   slist = (int*)(sh + O_SLIST);
    int*   ekeys = (int*)(sh + O_EKEYS);

    int t = threadIdx.x, wid = t >> 5, lane = t & 31;
    int nbd = blockIdx.x, n = nbd >> 2, b = nbd & 3;
    int es = g_offsets[n];
    int deg = g_offsets[n+1] - es;
    if (deg > MAXDEG) deg = MAXDEG;

    if (t < deg) ekeys[t] = g_sorted[es + t];

    // prologue: dst-side fixed smem
    for (int i = t; i < 256; i += 128)
        ((float4*)B1d)[i] = ((const float4*)&g_Bm[(size_t)nbd*2048])[i];
    for (int i = t; i < 384; i += 128) {
        int l = i >> 5, k = i & 31;
        stds[l*36 + k] = g_state[nbd*384 + i];
    }
    __syncthreads();

    // deterministic rank-sort of bin by edge id; store src node
    if (t < deg) {
        int key = ekeys[t], r = 0;
        for (int j = 0; j < deg; j++) r += (ekeys[j] < key);
        slist[r] = src[key];
    }
    __syncthreads();

    int lg = lane >> 3, hg = lane & 7, h4 = hg * 4;
    int l0 = lg * 3;

    // dst-side per-lane registers: P4 + mbd
    float4 p4m[3];
    {
        float4 md = *(const float4*)&g_mbd[nbd*32 + h4];
        #pragma unroll
        for (int j = 0; j < 3; j++) {
            float4 a = *(const float4*)&g_P4[nbd*384 + (l0 + j)*32 + h4];
            p4m[j].x = a.x + md.x; p4m[j].y = a.y + md.y;
            p4m[j].z = a.z + md.z; p4m[j].w = a.w + md.w;
        }
    }

    // per-warp staging buffers
    float* A2b  = sh + O_PW + wid*PW_WORDS;   // 2 x 1024
    float* stsS = A2b + 2048;                 // 2 x 432 (12*36)
    u32 sA2 = (u32)__cvta_generic_to_shared(A2b);
    u32 sSt = (u32)__cvta_generic_to_shared(stsS);

    int cnt = (deg > wid) ? ((deg - wid + 3) >> 2) : 0;

    u64 num[3][2], den[3][2];
    #pragma unroll
    for (int j = 0; j < 3; j++) { num[j][0]=num[j][1]=den[j][0]=den[j][1]=0ull; }

    float4 p1c[3], mbc;

    for (int m = 0; m < cnt + 1; m++) {
        // stage edge m (cp.async) + register-prefetch its P1/mbs
        if (m < cnt) {
            int nbs = slist[wid + 4*m]*4 + b;
            int v = m & 1;
            const float* pa = &g_A[(size_t)nbs*2048 + 1024];
            #pragma unroll
            for (int r = 0; r < 8; r++) {
                int c = lane + 32*r;
                cpa16(sA2 + v*4096 + c*16, pa + c*4);
            }
            const float* ps = &g_state[nbs*384];
            #pragma unroll
            for (int r = 0; r < 3; r++) {
                int c = lane + 32*r;
                int l = c >> 3, c4 = (c & 7) * 4;
                cpa16(sSt + v*1728 + (l*36 + c4)*4, ps + c*4);
            }
            cpcommit();
        }
        // compute edge m-1
        if (m > 0) {
            int v = (m - 1) & 1;
            if (m < cnt) cpwait<1>(); else cpwait<0>();
            __syncwarp();
            float* A2v = A2b + v*1024;
            float* stv = stsS + v*432;

            u64 att[3][2];
            #pragma unroll
            for (int j = 0; j < 3; j++) {
                att[j][0] = pk2(p1c[j].x + p4m[j].x + mbc.x, p1c[j].y + p4m[j].y + mbc.y);
                att[j][1] = pk2(p1c[j].z + p4m[j].z + mbc.z, p1c[j].w + p4m[j].w + mbc.w);
            }
            #pragma unroll
            for (int k4 = 0; k4 < 32; k4 += 4) {
                float4 ssv[3], ddv[3];
                #pragma unroll
                for (int j = 0; j < 3; j++) {
                    int l = l0 + j;
                    ssv[j] = *(float4*)&stv[l*36 + k4];
                    ddv[j] = *(float4*)&stds[l*36 + k4];
                }
                #pragma unroll
                for (int kk = 0; kk < 4; kk++) {
                    int k = k4 + kk;
                    ulonglong2 bb = *(const ulonglong2*)&B1d[k*32 + h4];
                    ulonglong2 aa = *(const ulonglong2*)&A2v[k*32 + h4];
                    #pragma unroll
                    for (int j = 0; j < 3; j++) {
                        float sf = (kk == 0) ? ssv[j].x : (kk == 1) ? ssv[j].y
                                 : (kk == 2) ? ssv[j].z : ssv[j].w;
                        float df = (kk == 0) ? ddv[j].x : (kk == 1) ? ddv[j].y
                                 : (kk == 2) ? ddv[j].z : ddv[j].w;
                        u64 ss = pk2s(sf), dd = pk2s(df);
                        att[j][0] = fma2(ss, bb.x, att[j][0]);
                        att[j][1] = fma2(ss, bb.y, att[j][1]);
                        att[j][0] = fma2(dd, aa.x, att[j][0]);
                        att[j][1] = fma2(dd, aa.y, att[j][1]);
                    }
                }
            }
            #pragma unroll
            for (int j = 0; j < 3; j++) {
                int l = l0 + j;
                float a0,a1,a2,a3;
                upk2(a0, a1, att[j][0]); upk2(a2, a3, att[j][1]);
                float e0 = __expf(a0), e1 = __expf(a1), e2 = __expf(a2), e3 = __expf(a3);
                u64 ep0 = pk2(e0, e1), ep1 = pk2(e2, e3);
                den[j][0] = add2(den[j][0], ep0);
                den[j][1] = add2(den[j][1], ep1);
                float4 sv = *(float4*)&stv[l*36 + h4];
                num[j][0] = fma2(ep0, pk2(sv.x, sv.y), num[j][0]);
                num[j][1] = fma2(ep1, pk2(sv.z, sv.w), num[j][1]);
            }
            __syncwarp();
        }
        // register prefetch P1/mbs for the edge just staged (consumed next iter)
        if (m < cnt) {
            int nbs = slist[wid + 4*m]*4 + b;
            #pragma unroll
            for (int j = 0; j < 3; j++)
                p1c[j] = __ldg((const float4*)&g_P1[nbs*384 + (l0 + j)*32 + h4]);
            mbc = __ldg((const float4*)&g_mbs[nbs*32 + h4]);
        }
    }

    // write this warp's partial num/den into its (now dead) A2 buffer
    {
        float* cw = A2b;
        #pragma unroll
        for (int j = 0; j < 3; j++) {
            int l = l0 + j;
            float n0,n1,n2,n3,d0,d1,d2,d3;
            upk2(n0, n1, num[j][0]); upk2(n2, n3, num[j][1]);
            upk2(d0, d1, den[j][0]); upk2(d2, d3, den[j][1]);
            float4 nv = {n0, n1, n2, n3};
            float4 dv = {d0, d1, d2, d3};
            *(float4*)&cw[l*32 + h4]       = nv;
            *(float4*)&cw[384 + l*32 + h4] = dv;
        }
    }
    __syncthreads();

    // combine across warps -> news
    for (int idx = t; idx < 384; idx += 128) {
        float ns = 0.f, ds = 0.f;
        #pragma unroll
        for (int w = 0; w < 4; w++) {
            const float* cw = sh + O_PW + w*PW_WORDS;
            ns += cw[idx];
            ds += cw[384 + idx];
        }
        news[idx] = __fdividef(ns, ds == 0.f ? 1.f : ds);
    }
    __syncthreads();

    // output projection (W_out via L1-resident LDG)
    for (int oi = t; oi < L1D*OUTD; oi += 128) {
        int l = oi >> 4, o = oi & 15;
        float acc = __ldg(&b_out[o]);
        #pragma unroll
        for (int h = 0; h < HID; h++)
            acc = fmaf(news[l*32 + h], __ldg(&W_out[h*16 + o]), acc);
        out[((b*L1D + l)*N_NODES + n)*OUTD + o] = acc;
    }
}

// ---------------- launch ----------------
extern "C" void kernel_launch(void* const* d_in, const int* in_sizes, int n_in,
                              void* d_out, int out_size) {
    const float* long_states = (const float*)d_in[0];   // [B,N,REF]
    const float* short_in    = (const float*)d_in[1];   // [B,L1,N,IN]
    const int*   src         = (const int*)d_in[2];
    const int*   dst         = (const int*)d_in[3];
    const float* W_in        = (const float*)d_in[4];
    const float* b_in        = (const float*)d_in[5];
    const float* W_metaW     = (const float*)d_in[6];
    const float* b_metaW     = (const float*)d_in[7];
    const float* W_metab     = (const float*)d_in[8];
    const float* b_metab     = (const float*)d_in[9];
    const float* W_out       = (const float*)d_in[10];
    const float* b_out       = (const float*)d_in[11];
    float* out = (float*)d_out;

    cudaFuncSetAttribute(k_main, cudaFuncAttributeMaxDynamicSharedMemorySize, SMEM_MAIN);

    k_state<<<N_NODES, 256>>>(short_in, W_in, b_in);   // also zeroes g_counts
    k_hist<<<(N_EDGES + 255)/256, 256>>>(dst);
    k_meta<<<dim3(NB/32, 2048/128), 128>>>(long_states, W_metaW, b_metaW);
    k_scan<<<1, 1024>>>();
    k_scatter<<<(N_EDGES + 255)/256, 256>>>(dst);
    k_pmb<<<NB, 128>>>(long_states, W_metab, b_metab);
    k_main<<<NB, 128, SMEM_MAIN>>>(src, W_out, b_out, out);
}

// round 7
// speedup vs baseline: 1.6197x; 1.0391x over previous
#include <cuda_runtime.h>

#define N_NODES 2000
#define N_EDGES 16000
#define BB 4
#define L1D 12
#define IN_DIM 16
#define REF 32
#define HID 32
#define OUTD 16
#define NB (N_NODES*BB)   // 8000
#define MAXDEG 96

typedef unsigned long long u64;
typedef unsigned int u32;

// ---------------- scratch (device globals; no allocation) ----------------
__device__ float g_state[NB*L1D*HID];   // [n][b][l][h]
__device__ float g_A[NB*2048];          // A[nb][c], c=k*32+h, k=0..63 (b_metaW folded in)
__device__ float g_Bm[NB*2048];         // Bm[nb][c]
__device__ float g_P1[NB*L1D*HID];      // state @ A1
__device__ float g_P4[NB*L1D*HID];      // state @ B2
__device__ float g_mbs[NB*HID];
__device__ float g_mbd[NB*HID];
__device__ int   g_counts[N_NODES];
__device__ int   g_cursor[N_NODES];
__device__ int   g_offsets[N_NODES+1];
__device__ int   g_sorted[N_EDGES];

// ---------------- f32x2 packed helpers (Blackwell) ----------------
__device__ __forceinline__ u64 pk2(float lo, float hi) {
    u64 r; asm("mov.b64 %0, {%1,%2};" : "=l"(r) : "f"(lo), "f"(hi)); return r;
}
__device__ __forceinline__ u64 pk2s(float v) { return pk2(v, v); }
__device__ __forceinline__ void upk2(float& lo, float& hi, u64 v) {
    asm("mov.b64 {%0,%1}, %2;" : "=f"(lo), "=f"(hi) : "l"(v));
}
__device__ __forceinline__ u64 fma2(u64 a, u64 b, u64 c) {
    u64 d; asm("fma.rn.f32x2 %0, %1, %2, %3;" : "=l"(d) : "l"(a), "l"(b), "l"(c)); return d;
}
__device__ __forceinline__ u64 add2(u64 a, u64 b) {
    u64 d; asm("add.rn.f32x2 %0, %1, %2;" : "=l"(d) : "l"(a), "l"(b)); return d;
}

// ---------------- cp.async helpers ----------------
__device__ __forceinline__ void cpa16(u32 s, const void* g) {
    asm volatile("cp.async.cg.shared.global [%0], [%1], 16;" :: "r"(s), "l"(g));
}
__device__ __forceinline__ void cpcommit() {
    asm volatile("cp.async.commit_group;");
}
template<int N> __device__ __forceinline__ void cpwait() {
    asm volatile("cp.async.wait_group %0;" :: "n"(N));
}

// ---------------- K1: state = x @ W_in + b_in  (node-major); zero hist ----------------
__global__ void k_state(const float* __restrict__ x, const float* __restrict__ W_in,
                        const float* __restrict__ b_in) {
    int n = blockIdx.x;
    __shared__ float xs[BB*L1D*IN_DIM];   // 768
    __shared__ float ws[IN_DIM*HID];      // 512
    __shared__ float bs[HID];
    int t = threadIdx.x;   // 256
    if (t == 0) g_counts[n] = 0;          // zero histogram for the sort
    for (int i = t; i < IN_DIM*HID; i += 256) ws[i] = W_in[i];
    if (t < HID) bs[t] = b_in[t];
    for (int i = t; i < BB*L1D*IN_DIM; i += 256) {
        int bl = i / IN_DIM, ii = i % IN_DIM;
        int b = bl / L1D, l = bl % L1D;
        xs[i] = x[((b*L1D + l)*N_NODES + n)*IN_DIM + ii];
    }
    __syncthreads();
    for (int o = t; o < BB*L1D*HID; o += 256) {
        int h = o % HID, bl = o / HID;
        float acc = bs[h];
        #pragma unroll
        for (int i = 0; i < IN_DIM; i++)
            acc = fmaf(xs[bl*IN_DIM + i], ws[i*HID + h], acc);
        g_state[n*(BB*L1D*HID) + o] = acc;
    }
}

// ---------------- K2: per-node hypernetwork GEMM (f32x2), grid (250,16) ----------------
__global__ void __launch_bounds__(128) k_meta(const float* __restrict__ mk,
                                              const float* __restrict__ W,
                                              const float* __restrict__ bW) {
    const int NBT = 32, CT = 128;
    int nb0 = blockIdx.x * NBT;
    int c0  = blockIdx.y * CT;
    __shared__ __align__(16) float mks[NBT][REF];
    __shared__ __align__(16) float wA[REF][CT];
    __shared__ __align__(16) float wB[REF][CT];
    int t = threadIdx.x;   // 128
    for (int i = t; i < NBT*REF; i += 128) {
        int row = i / REF, r = i % REF;
        int nb = nb0 + row, n = nb >> 2, b = nb & 3;
        mks[row][r] = mk[(b*N_NODES + n)*REF + r];
    }
    for (int i = t; i < REF*CT/4; i += 128) {
        int r = (i*4) / CT, c = (i*4) % CT;
        *(float4*)&wA[r][c] = *(const float4*)&W[r*2048 + c0 + c];
        *(float4*)&wB[r][c] = *(const float4*)&W[(r + REF)*2048 + c0 + c];
    }
    __syncthreads();
    int tc = t & 15;
    int tr = t >> 4;
    int row0 = tr * 4, col0 = tc * 8;
    u64 accA[4][4], accB[4][4];
    #pragma unroll
    for (int i = 0; i < 4; i++)
        #pragma unroll
        for (int j = 0; j < 4; j++) { accA[i][j] = 0ull; accB[i][j] = 0ull; }
    #pragma unroll 8
    for (int r = 0; r < REF; r++) {
        ulonglong2 wa0 = *(const ulonglong2*)&wA[r][col0];
        ulonglong2 wa1 = *(const ulonglong2*)&wA[r][col0+4];
        ulonglong2 wb0 = *(const ulonglong2*)&wB[r][col0];
        ulonglong2 wb1 = *(const ulonglong2*)&wB[r][col0+4];
        #pragma unroll
        for (int i = 0; i < 4; i++) {
            u64 a = pk2s(mks[row0+i][r]);
            accA[i][0] = fma2(a, wa0.x, accA[i][0]);
            accA[i][1] = fma2(a, wa0.y, accA[i][1]);
            accA[i][2] = fma2(a, wa1.x, accA[i][2]);
            accA[i][3] = fma2(a, wa1.y, accA[i][3]);
            accB[i][0] = fma2(a, wb0.x, accB[i][0]);
            accB[i][1] = fma2(a, wb0.y, accB[i][1]);
            accB[i][2] = fma2(a, wb1.x, accB[i][2]);
            accB[i][3] = fma2(a, wb1.y, accB[i][3]);
        }
    }
    ulonglong2 bv0 = *(const ulonglong2*)&bW[c0 + col0];
    ulonglong2 bv1 = *(const ulonglong2*)&bW[c0 + col0 + 4];
    #pragma unroll
    for (int i = 0; i < 4; i++) {
        int nb = nb0 + row0 + i;
        ulonglong2 oa0, oa1, ob0, ob1;
        oa0.x = add2(accA[i][0], bv0.x); oa0.y = add2(accA[i][1], bv0.y);
        oa1.x = add2(accA[i][2], bv1.x); oa1.y = add2(accA[i][3], bv1.y);
        ob0.x = accB[i][0]; ob0.y = accB[i][1];
        ob1.x = accB[i][2]; ob1.y = accB[i][3];
        *(ulonglong2*)&g_A[nb*2048 + c0 + col0]      = oa0;
        *(ulonglong2*)&g_A[nb*2048 + c0 + col0 + 4]  = oa1;
        *(ulonglong2*)&g_Bm[nb*2048 + c0 + col0]     = ob0;
        *(ulonglong2*)&g_Bm[nb*2048 + c0 + col0 + 4] = ob1;
    }
}

// ---------------- K2b: P1 = state@A1, P4 = state@B2, mbs/mbd ----------------
__global__ void k_pmb(const float* __restrict__ mk, const float* __restrict__ Wmb,
                      const float* __restrict__ bmb) {
    int nb = blockIdx.x, n = nb >> 2, b = nb & 3;
    __shared__ float st[L1D*HID];
    __shared__ float A1[1024];
    __shared__ float B2[1024];
    __shared__ float mks[REF];
    int t = threadIdx.x;  // 128
    {
        const float4* ps = reinterpret_cast<const float4*>(&g_state[nb*L1D*HID]);
        float4* ss = reinterpret_cast<float4*>(st);
        for (int i = t; i < (L1D*HID)/4; i += 128) ss[i] = ps[i];
        const float4* pa = reinterpret_cast<const float4*>(&g_A[nb*2048]);
        const float4* pb = reinterpret_cast<const float4*>(&g_Bm[nb*2048 + 1024]);
        float4* sa = reinterpret_cast<float4*>(A1);
        float4* sb = reinterpret_cast<float4*>(B2);
        for (int i = t; i < 256; i += 128) { sa[i] = pa[i]; sb[i] = pb[i]; }
    }
    if (t < REF) mks[t] = mk[(b*N_NODES + n)*REF + t];
    __syncthreads();
    int h = t & 31, l0 = t >> 5;
    #pragma unroll
    for (int j = 0; j < 3; j++) {
        int l = l0 + 4*j;
        float p1 = 0.f, p4 = 0.f;
        #pragma unroll
        for (int k = 0; k < HID; k++) {
            float s = st[l*HID + k];
            p1 = fmaf(s, A1[k*32 + h], p1);
            p4 = fmaf(s, B2[k*32 + h], p4);
        }
        g_P1[nb*(L1D*HID) + l*32 + h] = p1;
        g_P4[nb*(L1D*HID) + l*32 + h] = p4;
    }
    if (t < HID) {
        float s1 = 0.f, s2 = bmb[t];
        #pragma unroll
        for (int r = 0; r < REF; r++) {
            s1 = fmaf(mks[r], Wmb[r*HID + t], s1);
            s2 = fmaf(mks[r], Wmb[(r + REF)*HID + t], s2);
        }
        g_mbs[nb*HID + t] = s1;
        g_mbd[nb*HID + t] = s2;
    }
}

// ---------------- K3: parallel counting sort by dst (bin order fixed in k_main) ----------------
__global__ void k_hist(const int* __restrict__ dst) {
    int e = blockIdx.x*blockDim.x + threadIdx.x;
    if (e < N_EDGES) atomicAdd(&g_counts[dst[e]], 1);
}
__global__ void k_scan() {
    __shared__ int sb[1024];
    int t = threadIdx.x;
    int i0 = 2*t, i1 = 2*t + 1;
    int a0 = (i0 < N_NODES) ? g_counts[i0] : 0;
    int a1 = (i1 < N_NODES) ? g_counts[i1] : 0;
    sb[t] = a0 + a1;
    __syncthreads();
    for (int off = 1; off < 1024; off <<= 1) {
        int v = (t >= off) ? sb[t - off] : 0;
        __syncthreads();
        sb[t] += v;
        __syncthreads();
    }
    int excl = sb[t] - (a0 + a1);
    if (i0 < N_NODES) { g_offsets[i0] = excl;      g_cursor[i0] = excl; }
    if (i1 < N_NODES) { g_offsets[i1] = excl + a0; g_cursor[i1] = excl + a0; }
    if (t == 1023) g_offsets[N_NODES] = sb[1023];
}
__global__ void k_scatter(const int* __restrict__ dst) {
    int e = blockIdx.x*blockDim.x + threadIdx.x;
    if (e < N_EDGES) {
        int d = dst[e];
        int pos = atomicAdd(&g_cursor[d], 1);
        g_sorted[pos] = e;
    }
}

// ---------------- K4: k_main — block = node n; warp = batch b; warp owns whole bin ----------------
// smem layout (float words):
//   [0..96)      ekeys (int)
//   [96..192)    slist (int)
//   [192 + wid*4368):  per-warp region:
//        B1d  +0     (1024)
//        A2b  +1024  (2 x 1024)
//        stsS +3072  (2 x 432)
//        stds +3936  (432)
#define PWW 4368
#define SMEM_MAIN ((192 + 4*PWW)*4)   // 70656 bytes -> 3 blocks/SM

__global__ void __launch_bounds__(128, 3) k_main(const int* __restrict__ src,
                                                 const float* __restrict__ W_out,
                                                 const float* __restrict__ b_out,
                                                 float* __restrict__ out) {
    extern __shared__ __align__(16) float sh[];
    int* ekeys = (int*)sh;
    int* slist = (int*)sh + 96;

    int t = threadIdx.x, wid = t >> 5, lane = t & 31;
    int n = blockIdx.x, b = wid;
    int nbd = n*4 + b;
    int es = g_offsets[n];
    int deg = g_offsets[n+1] - es;
    int degc = (deg < MAXDEG) ? deg : MAXDEG;

    if (t < degc) ekeys[t] = g_sorted[es + t];

    float* W   = sh + 192 + wid*PWW;
    float* B1d  = W;            // 1024
    float* A2b  = W + 1024;     // 2 x 1024
    float* stsS = W + 3072;     // 2 x 432
    float* stds = W + 3936;     // 432

    // per-warp prologue: dst-side fixed data
    for (int i = lane; i < 256; i += 32)
        ((float4*)B1d)[i] = ((const float4*)&g_Bm[(size_t)nbd*2048])[i];
    for (int i = lane; i < 96; i += 32) {
        int l = i >> 3, c4 = (i & 7) * 4;
        *(float4*)&stds[l*36 + c4] = ((const float4*)&g_state[nbd*384])[i];
    }
    __syncthreads();

    // deterministic rank-sort of bin by edge id (shared across the 4 b-warps)
    if (t < degc) {
        int key = ekeys[t], r = 0;
        for (int j = 0; j < degc; j++) r += (ekeys[j] < key);
        slist[r] = src[key];
    }
    __syncthreads();

    int lg = lane >> 3, hg = lane & 7, h4 = hg * 4;
    int l0 = lg * 3;

    // dst-side per-lane registers: P4 + mbd
    float4 p4m[3];
    {
        float4 md = *(const float4*)&g_mbd[nbd*32 + h4];
        #pragma unroll
        for (int j = 0; j < 3; j++) {
            float4 a = *(const float4*)&g_P4[nbd*384 + (l0 + j)*32 + h4];
            p4m[j].x = a.x + md.x; p4m[j].y = a.y + md.y;
            p4m[j].z = a.z + md.z; p4m[j].w = a.w + md.w;
        }
    }

    u32 sA2 = (u32)__cvta_generic_to_shared(A2b);
    u32 sSt = (u32)__cvta_generic_to_shared(stsS);

    u64 num[3][2], den[3][2];
    #pragma unroll
    for (int j = 0; j < 3; j++) { num[j][0]=num[j][1]=den[j][0]=den[j][1]=0ull; }

    float4 p1c[3], mbc;

    // compute body for one staged edge (buffers v), using p1c/mbc regs
    auto computeEdge = [&](int v) {
        float* A2v = A2b + v*1024;
        float* stv = stsS + v*432;
        u64 att[3][2];
        #pragma unroll
        for (int j = 0; j < 3; j++) {
            att[j][0] = pk2(p1c[j].x + p4m[j].x + mbc.x, p1c[j].y + p4m[j].y + mbc.y);
            att[j][1] = pk2(p1c[j].z + p4m[j].z + mbc.z, p1c[j].w + p4m[j].w + mbc.w);
        }
        #pragma unroll
        for (int k4 = 0; k4 < 32; k4 += 4) {
            float4 ssv[3], ddv[3];
            #pragma unroll
            for (int j = 0; j < 3; j++) {
                int l = l0 + j;
                ssv[j] = *(float4*)&stv[l*36 + k4];
                ddv[j] = *(float4*)&stds[l*36 + k4];
            }
            #pragma unroll
            for (int kk = 0; kk < 4; kk++) {
                int k = k4 + kk;
                ulonglong2 bb = *(const ulonglong2*)&B1d[k*32 + h4];
                ulonglong2 aa = *(const ulonglong2*)&A2v[k*32 + h4];
                #pragma unroll
                for (int j = 0; j < 3; j++) {
                    float sf = (kk == 0) ? ssv[j].x : (kk == 1) ? ssv[j].y
                             : (kk == 2) ? ssv[j].z : ssv[j].w;
                    float df = (kk == 0) ? ddv[j].x : (kk == 1) ? ddv[j].y
                             : (kk == 2) ? ddv[j].z : ddv[j].w;
                    u64 ss = pk2s(sf), dd = pk2s(df);
                    att[j][0] = fma2(ss, bb.x, att[j][0]);
                    att[j][1] = fma2(ss, bb.y, att[j][1]);
                    att[j][0] = fma2(dd, aa.x, att[j][0]);
                    att[j][1] = fma2(dd, aa.y, att[j][1]);
                }
            }
        }
        #pragma unroll
        for (int j = 0; j < 3; j++) {
            int l = l0 + j;
            float a0,a1,a2,a3;
            upk2(a0, a1, att[j][0]); upk2(a2, a3, att[j][1]);
            float e0 = __expf(a0), e1 = __expf(a1), e2 = __expf(a2), e3 = __expf(a3);
            u64 ep0 = pk2(e0, e1), ep1 = pk2(e2, e3);
            den[j][0] = add2(den[j][0], ep0);
            den[j][1] = add2(den[j][1], ep1);
            float4 sv = *(float4*)&stv[l*36 + h4];
            num[j][0] = fma2(ep0, pk2(sv.x, sv.y), num[j][0]);
            num[j][1] = fma2(ep1, pk2(sv.z, sv.w), num[j][1]);
        }
    };

    // pipelined main loop over this warp's whole bin
    for (int m = 0; m < degc + 1; m++) {
        if (m < degc) {
            int nbs = slist[m]*4 + b;
            int v = m & 1;
            const float* pa = &g_A[(size_t)nbs*2048 + 1024];
            #pragma unroll
            for (int r = 0; r < 8; r++) {
                int c = lane + 32*r;
                cpa16(sA2 + v*4096 + c*16, pa + c*4);
            }
            const float* ps = &g_state[nbs*384];
            #pragma unroll
            for (int r = 0; r < 3; r++) {
                int c = lane + 32*r;
                int l = c >> 3, c4 = (c & 7) * 4;
                cpa16(sSt + v*1728 + (l*36 + c4)*4, ps + c*4);
            }
            cpcommit();
        }
        if (m > 0) {
            if (m < degc) cpwait<1>(); else cpwait<0>();
            __syncwarp();
            computeEdge((m - 1) & 1);
            __syncwarp();
        }
        if (m < degc) {
            int nbs = slist[m]*4 + b;
            #pragma unroll
            for (int j = 0; j < 3; j++)
                p1c[j] = __ldg((const float4*)&g_P1[nbs*384 + (l0 + j)*32 + h4]);
            mbc = __ldg((const float4*)&g_mbs[nbs*32 + h4]);
        }
    }

    // overflow fallback (deg > MAXDEG): synchronous, correct, rare
    for (int i = MAXDEG; i < deg; i++) {
        int nbs = src[g_sorted[es + i]]*4 + b;
        for (int c = lane; c < 256; c += 32)
            ((float4*)A2b)[c] = ((const float4*)&g_A[(size_t)nbs*2048 + 1024])[c];
        for (int c = lane; c < 96; c += 32) {
            int l = c >> 3, c4 = (c & 7) * 4;
            *(float4*)&stsS[l*36 + c4] = ((const float4*)&g_state[nbs*384])[c];
        }
        #pragma unroll
        for (int j = 0; j < 3; j++)
            p1c[j] = __ldg((const float4*)&g_P1[nbs*384 + (l0 + j)*32 + h4]);
        mbc = __ldg((const float4*)&g_mbs[nbs*32 + h4]);
        __syncwarp();
        computeEdge(0);
        __syncwarp();
    }

    // softmax finalize into news (reuse dead A2b), then output projection
    float* news = A2b;
    __syncwarp();
    #pragma unroll
    for (int j = 0; j < 3; j++) {
        int l = l0 + j;
        float n0,n1,n2,n3,d0,d1,d2,d3;
        upk2(n0, n1, num[j][0]); upk2(n2, n3, num[j][1]);
        upk2(d0, d1, den[j][0]); upk2(d2, d3, den[j][1]);
        float4 r;
        r.x = __fdividef(n0, d0 == 0.f ? 1.f : d0);
        r.y = __fdividef(n1, d1 == 0.f ? 1.f : d1);
        r.z = __fdividef(n2, d2 == 0.f ? 1.f : d2);
        r.w = __fdividef(n3, d3 == 0.f ? 1.f : d3);
        *(float4*)&news[l*32 + h4] = r;
    }
    __syncwarp();

    for (int oi = lane; oi < L1D*OUTD; oi += 32) {
        int l = oi >> 4, o = oi & 15;
        float acc = __ldg(&b_out[o]);
        #pragma unroll
        for (int h = 0; h < HID; h++)
            acc = fmaf(news[l*32 + h], __ldg(&W_out[h*16 + o]), acc);
        out[((b*L1D + l)*N_NODES + n)*OUTD + o] = acc;
    }
}

// ---------------- launch ----------------
extern "C" void kernel_launch(void* const* d_in, const int* in_sizes, int n_in,
                              void* d_out, int out_size) {
    const float* long_states = (const float*)d_in[0];   // [B,N,REF]
    const float* short_in    = (const float*)d_in[1];   // [B,L1,N,IN]
    const int*   src         = (const int*)d_in[2];
    const int*   dst         = (const int*)d_in[3];
    const float* W_in        = (const float*)d_in[4];
    const float* b_in        = (const float*)d_in[5];
    const float* W_metaW     = (const float*)d_in[6];
    const float* b_metaW     = (const float*)d_in[7];
    const float* W_metab     = (const float*)d_in[8];
    const float* b_metab     = (const float*)d_in[9];
    const float* W_out       = (const float*)d_in[10];
    const float* b_out       = (const float*)d_in[11];
    float* out = (float*)d_out;

    cudaFuncSetAttribute(k_main, cudaFuncAttributeMaxDynamicSharedMemorySize, SMEM_MAIN);

    k_state<<<N_NODES, 256>>>(short_in, W_in, b_in);   // also zeroes g_counts
    k_hist<<<(N_EDGES + 255)/256, 256>>>(dst);
    k_meta<<<dim3(NB/32, 2048/128), 128>>>(long_states, W_metaW, b_metaW);
    k_scan<<<1, 1024>>>();
    k_scatter<<<(N_EDGES + 255)/256, 256>>>(dst);
    k_pmb<<<NB, 128>>>(long_states, W_metab, b_metab);
    k_main<<<N_NODES, 128, SMEM_MAIN>>>(src, W_out, b_out, out);
}